// round 16
// baseline (speedup 1.0000x reference)
#include <cuda_runtime.h>
#include <cuda_fp16.h>
#include <math.h>
#include <stdint.h>

// Problem constants
#define BB   2
#define SS   2048
#define DD   4096
#define QH   32
#define KVH  8
#define HD   128
#define KVD  (KVH*HD)      // 1024
#define GROUP (QH/KVH)     // 4
#define TOK  (BB*SS)       // 4096
#define K2   (2*DD)        // 8192 : x split length [hi|lo]
#define NQKV (DD + 2*KVD)  // 6144

#define QSCALE (0.08838834764831845f * 1.4426950408889634f)

// ---------------------------------------------------------------------------
// Scratch
// ---------------------------------------------------------------------------
__device__ __align__(16) __half g_xc  [(size_t)TOK*K2];    // [xh | xl]
__device__ __align__(16) __half g_wqkv[(size_t)NQKV*DD];   // fp16 weights
__device__ __align__(16) __half g_woc [(size_t)DD*DD];
__device__ __align__(16) __half g_cc  [(size_t)TOK*DD];    // ctx, single fp16

__device__ __align__(16) __half g_qh[TOK*DD];
__device__ __align__(16) __half g_ql[TOK*DD];
__device__ __align__(16) __half g_kh[TOK*KVD];
__device__ __align__(16) __half g_vh[TOK*KVD];

// ---------------------------------------------------------------------------
// helpers
// ---------------------------------------------------------------------------
__device__ __forceinline__ uint32_t smem_u32(const void* p) {
    uint32_t a;
    asm("{ .reg .u64 t; cvta.to.shared.u64 t, %1; cvt.u32.u64 %0, t; }" : "=r"(a) : "l"(p));
    return a;
}

#define CP_ASYNC16(dst, src) \
    asm volatile("cp.async.cg.shared.global [%0], [%1], 16;" :: "r"(dst), "l"(src))
#define CP_COMMIT()   asm volatile("cp.async.commit_group;" ::: "memory")
#define CP_WAIT(n)    asm volatile("cp.async.wait_group %0;" :: "n"(n) : "memory")

#define LDM_X4(r0, r1, r2, r3, addr) \
    asm volatile("ldmatrix.sync.aligned.m8n8.x4.shared.b16 {%0,%1,%2,%3}, [%4];" \
        : "=r"(r0), "=r"(r1), "=r"(r2), "=r"(r3) : "r"(addr))

#define LDM_X4T(r0, r1, r2, r3, addr) \
    asm volatile("ldmatrix.sync.aligned.m8n8.x4.trans.shared.b16 {%0,%1,%2,%3}, [%4];" \
        : "=r"(r0), "=r"(r1), "=r"(r2), "=r"(r3) : "r"(addr))

#define MMA16816(d, a, b) \
    asm volatile("mma.sync.aligned.m16n8k16.row.col.f32.f16.f16.f32 " \
        "{%0,%1,%2,%3},{%4,%5,%6,%7},{%8,%9},{%0,%1,%2,%3};" \
        : "+f"((d)[0]), "+f"((d)[1]), "+f"((d)[2]), "+f"((d)[3]) \
        : "r"((a)[0]), "r"((a)[1]), "r"((a)[2]), "r"((a)[3]), \
          "r"((b)[0]), "r"((b)[1]))

__device__ __forceinline__ uint32_t pack_f16(float a, float b) {
    __half2 h = __floats2half2_rn(a, b);
    return *reinterpret_cast<uint32_t*>(&h);
}
__device__ __forceinline__ float2 unpack_f16(uint32_t u) {
    __half2 h = *reinterpret_cast<__half2*>(&u);
    return __half22float2(h);
}
__device__ __forceinline__ float ex2f(float x) {
    float r; asm("ex2.approx.f32 %0, %1;" : "=f"(r) : "f"(x)); return r;
}

// ---------------------------------------------------------------------------
// Fused conversion kernel (one launch, 5 regions)
// ---------------------------------------------------------------------------
#define CN0 (TOK*DD/4)
#define CN1 (DD*DD/4)
#define CN2 (KVD*DD/4)
#define CN3 (KVD*DD/4)
#define CN4 (DD*DD/4)
#define CNTOT (CN0+CN1+CN2+CN3+CN4)

__global__ void convert_all(const float* __restrict__ xs,
                            const float* __restrict__ Wq,
                            const float* __restrict__ Wk,
                            const float* __restrict__ Wv,
                            const float* __restrict__ Wo,
                            __half* __restrict__ xc,
                            __half* __restrict__ wqkv,
                            __half* __restrict__ woc)
{
    int gid = blockIdx.x * blockDim.x + threadIdx.x;
    if (gid >= CNTOT) return;
    if (gid < CN0) {
        float4 v = ((const float4*)xs)[gid];
        int K4 = DD >> 2;
        int r  = gid / K4;
        int k  = (gid - r * K4) << 2;
        uint32_t h0 = pack_f16(v.x, v.y);
        uint32_t h1 = pack_f16(v.z, v.w);
        float2 f0 = unpack_f16(h0), f1 = unpack_f16(h1);
        uint32_t l0 = pack_f16(v.x - f0.x, v.y - f0.y);
        uint32_t l1 = pack_f16(v.z - f1.x, v.w - f1.y);
        __half* row = xc + (size_t)r * K2;
        *(uint2*)(row + k)      = make_uint2(h0, h1);
        *(uint2*)(row + DD + k) = make_uint2(l0, l1);
        return;
    }
    gid -= CN0;
    const float* src;
    __half* dst;
    if (gid < CN1)                 { src = Wq; dst = wqkv; }
    else if (gid < CN1 + CN2)      { gid -= CN1; src = Wk; dst = wqkv + (size_t)DD*DD; }
    else if (gid < CN1 + CN2 + CN3){ gid -= CN1 + CN2; src = Wv; dst = wqkv + (size_t)(DD+KVD)*DD; }
    else                           { gid -= CN1 + CN2 + CN3; src = Wo; dst = woc; }
    float4 v = ((const float4*)src)[gid];
    ((uint2*)dst)[gid] = make_uint2(pack_f16(v.x, v.y), pack_f16(v.z, v.w));
}

// ---------------------------------------------------------------------------
// common GEMM geometry
// ---------------------------------------------------------------------------
#define CTM   128
#define CTN   128
#define GBK   64
#define NCH   (DD / GBK)            // 64
#define ROWB  144                   // 64 fp16 (128B) + 16B pad
#define TILE  (128 * ROWB)          // 18432

// ---------------------------------------------------------------------------
// QKV GEMM: Q columns = (xh + xl) @ W^T (2-pass), K/V columns = xh @ W^T.
// 2 stages of [Ah|Al|B] (55 KB), occ 2.  Fused rope + q hi/lo split.
// ---------------------------------------------------------------------------
#define NST   2
#define STAGE (3 * TILE)            // 55296
#define GSMEM (NST * STAGE)         // 110592

__global__ __launch_bounds__(256, 2) void gemm_qkv(
    const __half* __restrict__ A, const __half* __restrict__ B,
    const float* __restrict__ bq, const float* __restrict__ bk,
    const float* __restrict__ bv,
    const float* __restrict__ fc, const int* __restrict__ spos,
    __half* __restrict__ qh, __half* __restrict__ ql,
    __half* __restrict__ kh, __half* __restrict__ vh)
{
    extern __shared__ char smraw[];
    const int t    = threadIdx.x;
    const int lane = t & 31;
    const int wid  = t >> 5;
    const int wm   = wid & 1;
    const int wn   = wid >> 1;
    const int m0   = blockIdx.x * CTM;
    const int n0   = blockIdx.y * CTN;
    const bool twop = (n0 < DD);          // q segment: 2-pass
    const uint32_t sb = smem_u32(smraw);

    float acc[4][4][4];
#pragma unroll
    for (int i = 0; i < 4; i++)
#pragma unroll
        for (int j = 0; j < 4; j++)
#pragma unroll
            for (int r = 0; r < 4; r++) acc[i][j][r] = 0.f;

    const __half* Ahs[4];
    const __half* Bs[4];
    uint32_t doff[4];
#pragma unroll
    for (int i = 0; i < 4; i++) {
        int id  = t + i * 256;
        int row = id >> 3;
        int c8  = id & 7;
        doff[i] = row * ROWB + c8 * 16;
        Ahs[i]  = A + (size_t)(m0 + row) * K2 + c8 * 8;
        Bs[i]   = B + (size_t)(n0 + row) * DD + c8 * 8;
    }

#define LOAD_STAGE(st, k0) do {                                        \
    uint32_t base = sb + (st) * STAGE;                                 \
    _Pragma("unroll")                                                  \
    for (int i = 0; i < 4; i++)                                        \
        CP_ASYNC16(base + doff[i], Ahs[i] + (k0));                     \
    if (twop) {                                                        \
        _Pragma("unroll")                                              \
        for (int i = 0; i < 4; i++)                                    \
            CP_ASYNC16(base + TILE + doff[i], Ahs[i] + DD + (k0));     \
    }                                                                  \
    _Pragma("unroll")                                                  \
    for (int i = 0; i < 4; i++)                                        \
        CP_ASYNC16(base + 2 * TILE + doff[i], Bs[i] + (k0));           \
} while (0)

    LOAD_STAGE(0, 0);
    CP_COMMIT();

    const uint32_t aoffs = (wm * 64 + (lane & 15)) * ROWB + ((lane >> 4) << 4);
    const uint32_t boffs = (wn * 32 + (lane & 15)) * ROWB + ((lane >> 4) << 4);

    for (int c = 0; c < NCH; c++) {
        const int st = c & 1;
        CP_WAIT(0);
        __syncthreads();
        if (c + 1 < NCH) {
            LOAD_STAGE(st ^ 1, (c + 1) * GBK);
            CP_COMMIT();
        }

        const uint32_t ab  = sb + st * STAGE;
        const uint32_t ab2 = ab + TILE;
        const uint32_t bb  = ab + 2 * TILE;

#pragma unroll
        for (int ks = 0; ks < 4; ks++) {
            uint32_t a[4][4], a2[4][4];
            uint32_t bf[4][2];
#pragma unroll
            for (int mi = 0; mi < 4; mi++) {
                LDM_X4(a[mi][0], a[mi][1], a[mi][2], a[mi][3],
                       ab + aoffs + mi * 16 * ROWB + ks * 32);
            }
            if (twop) {
#pragma unroll
                for (int mi = 0; mi < 4; mi++)
                    LDM_X4(a2[mi][0], a2[mi][1], a2[mi][2], a2[mi][3],
                           ab2 + aoffs + mi * 16 * ROWB + ks * 32);
            }
#pragma unroll
            for (int p = 0; p < 2; p++) {
                uint32_t r0, r1, r2, r3;
                LDM_X4(r0, r1, r2, r3, bb + boffs + p * 16 * ROWB + ks * 32);
                bf[2*p][0]   = r0; bf[2*p][1]   = r2;
                bf[2*p+1][0] = r1; bf[2*p+1][1] = r3;
            }
#pragma unroll
            for (int mi = 0; mi < 4; mi++)
#pragma unroll
                for (int ni = 0; ni < 4; ni++)
                    MMA16816(acc[mi][ni], a[mi], bf[ni]);
            if (twop) {
#pragma unroll
                for (int mi = 0; mi < 4; mi++)
#pragma unroll
                    for (int ni = 0; ni < 4; ni++)
                        MMA16816(acc[mi][ni], a2[mi], bf[ni]);
            }
        }
    }
#undef LOAD_STAGE

    // fused QKV epilogue
    const int spv = spos[0];
    int seg, cbase;
    if (n0 < DD)            { seg = 0; cbase = 0; }
    else if (n0 < DD + KVD) { seg = 1; cbase = DD; }
    else                    { seg = 2; cbase = DD + KVD; }
    const float* bias = (seg == 0) ? bq : (seg == 1 ? bk : bv);
    __half* dh = (seg == 0) ? qh : (seg == 1 ? kh : vh);
    const int   ldd = (seg == 0) ? DD : KVD;
    const float sc  = (seg == 0) ? QSCALE : 1.0f;

#pragma unroll
    for (int mi = 0; mi < 4; mi++) {
        int ra = m0 + wm * 64 + mi * 16 + (lane >> 2);
        int rb = ra + 8;
        int sa  = ra & (SS - 1);
        int sbt = rb & (SS - 1);
#pragma unroll
        for (int ni = 0; ni < 4; ni++) {
            int c  = n0 + wn * 32 + ni * 8 + (lane & 3) * 2;
            int cl = c - cbase;
            float b0 = bias[cl], b1 = bias[cl + 1];
            float v0 = acc[mi][ni][0] + b0, v1 = acc[mi][ni][1] + b1;
            float v2 = acc[mi][ni][2] + b0, v3 = acc[mi][ni][3] + b1;
            if (seg < 2) {
                int p = (c & 127) >> 1;
                float2 fa = *(const float2*)(fc + ((size_t)(spv + sa)  * 64 + p) * 2);
                float2 fb = *(const float2*)(fc + ((size_t)(spv + sbt) * 64 + p) * 2);
                float o0 = (v0 * fa.x - v1 * fa.y) * sc;
                float o1 = (v0 * fa.y + v1 * fa.x) * sc;
                float o2 = (v2 * fb.x - v3 * fb.y) * sc;
                float o3 = (v2 * fb.y + v3 * fb.x) * sc;
                v0 = o0; v1 = o1; v2 = o2; v3 = o3;
            }
            uint32_t h0 = pack_f16(v0, v1);
            uint32_t h1 = pack_f16(v2, v3);
            *(uint32_t*)(dh + (size_t)ra * ldd + cl) = h0;
            *(uint32_t*)(dh + (size_t)rb * ldd + cl) = h1;
            if (seg == 0) {
                float2 f0 = unpack_f16(h0), f1 = unpack_f16(h1);
                *(uint32_t*)(ql + (size_t)ra * ldd + cl) = pack_f16(v0 - f0.x, v1 - f0.y);
                *(uint32_t*)(ql + (size_t)rb * ldd + cl) = pack_f16(v2 - f1.x, v3 - f1.y);
            }
        }
    }
}

// ---------------------------------------------------------------------------
// Output projection: single-pass fp16 GEMM (R15 version, measured-neutral
// B double buffer kept). 3 stages of [A|B], occ 2, CP_WAIT(1).
// ---------------------------------------------------------------------------
#define ONST   3
#define OSTAGE (2 * TILE)           // 36864
#define OSMEM  (ONST * OSTAGE)      // 110592

__global__ __launch_bounds__(256, 2) void gemm_out(
    const __half* __restrict__ A, const __half* __restrict__ B,
    const float* __restrict__ bias, float* __restrict__ C, int N)
{
    extern __shared__ char smraw[];
    const int t    = threadIdx.x;
    const int lane = t & 31;
    const int wid  = t >> 5;
    const int wm   = wid & 1;
    const int wn   = wid >> 1;
    const int m0   = blockIdx.x * CTM;
    const int n0   = blockIdx.y * CTN;
    const uint32_t sb = smem_u32(smraw);

    float acc[4][4][4];
#pragma unroll
    for (int i = 0; i < 4; i++)
#pragma unroll
        for (int j = 0; j < 4; j++)
#pragma unroll
            for (int r = 0; r < 4; r++) acc[i][j][r] = 0.f;

    const __half* As[4];
    const __half* Bs[4];
    uint32_t doff[4];
#pragma unroll
    for (int i = 0; i < 4; i++) {
        int id  = t + i * 256;
        int row = id >> 3;
        int c8  = id & 7;
        doff[i] = row * ROWB + c8 * 16;
        As[i]   = A + (size_t)(m0 + row) * DD + c8 * 8;
        Bs[i]   = B + (size_t)(n0 + row) * DD + c8 * 8;
    }

#define OLOAD(st, k0) do {                                             \
    uint32_t base = sb + (st) * OSTAGE;                                \
    _Pragma("unroll")                                                  \
    for (int i = 0; i < 4; i++)                                        \
        CP_ASYNC16(base + doff[i], As[i] + (k0));                      \
    _Pragma("unroll")                                                  \
    for (int i = 0; i < 4; i++)                                        \
        CP_ASYNC16(base + TILE + doff[i], Bs[i] + (k0));               \
} while (0)

    OLOAD(0, 0);
    CP_COMMIT();
    OLOAD(1, GBK);
    CP_COMMIT();

    const uint32_t aoffs = (wm * 64 + (lane & 15)) * ROWB + ((lane >> 4) << 4);
    const uint32_t boffs = (wn * 32 + (lane & 15)) * ROWB + ((lane >> 4) << 4);

    int st = 0;
    for (int c = 0; c < NCH; c++) {
        CP_WAIT(1);
        __syncthreads();
        if (c + 2 < NCH) {
            int st2 = st + 2; if (st2 >= ONST) st2 -= ONST;
            OLOAD(st2, (c + 2) * GBK);
        }
        CP_COMMIT();

        const uint32_t ab = sb + st * OSTAGE;
        const uint32_t bb = ab + TILE;

        uint32_t bf[2][4][2];
        {
            uint32_t r0, r1, r2, r3;
            LDM_X4(r0, r1, r2, r3, bb + boffs);
            bf[0][0][0] = r0; bf[0][0][1] = r2;
            bf[0][1][0] = r1; bf[0][1][1] = r3;
            LDM_X4(r0, r1, r2, r3, bb + boffs + 16 * ROWB);
            bf[0][2][0] = r0; bf[0][2][1] = r2;
            bf[0][3][0] = r1; bf[0][3][1] = r3;
        }

#pragma unroll
        for (int ks = 0; ks < 4; ks++) {
            const int cur = ks & 1;
            uint32_t a[4][4];
#pragma unroll
            for (int mi = 0; mi < 4; mi++)
                LDM_X4(a[mi][0], a[mi][1], a[mi][2], a[mi][3],
                       ab + aoffs + mi * 16 * ROWB + ks * 32);
            if (ks < 3) {
                uint32_t r0, r1, r2, r3;
                LDM_X4(r0, r1, r2, r3, bb + boffs + (ks + 1) * 32);
                bf[cur^1][0][0] = r0; bf[cur^1][0][1] = r2;
                bf[cur^1][1][0] = r1; bf[cur^1][1][1] = r3;
                LDM_X4(r0, r1, r2, r3, bb + boffs + 16 * ROWB + (ks + 1) * 32);
                bf[cur^1][2][0] = r0; bf[cur^1][2][1] = r2;
                bf[cur^1][3][0] = r1; bf[cur^1][3][1] = r3;
            }
#pragma unroll
            for (int mi = 0; mi < 4; mi++)
#pragma unroll
                for (int ni = 0; ni < 4; ni++)
                    MMA16816(acc[mi][ni], a[mi], bf[cur][ni]);
        }
        if (++st == ONST) st = 0;
    }
#undef OLOAD

#pragma unroll
    for (int mi = 0; mi < 4; mi++) {
        int r0 = m0 + wm * 64 + mi * 16 + (lane >> 2);
#pragma unroll
        for (int ni = 0; ni < 4; ni++) {
            int col = n0 + wn * 32 + ni * 8 + (lane & 3) * 2;
            float2 bv2 = *(const float2*)(bias + col);
            float2 o0 = make_float2(acc[mi][ni][0] + bv2.x, acc[mi][ni][1] + bv2.y);
            float2 o1 = make_float2(acc[mi][ni][2] + bv2.x, acc[mi][ni][3] + bv2.y);
            *(float2*)(C + (size_t)r0 * N + col)       = o0;
            *(float2*)(C + (size_t)(r0 + 8) * N + col) = o1;
        }
    }
}

// ---------------------------------------------------------------------------
// Tensor-core causal flash attention, fp16, BN=128 KV tiles.
// Q (hi+lo) in registers; K,V single fp16; P single fp16; 2-stage 128-row ring.
// ---------------------------------------------------------------------------
#define AROW     272
#define AKT_SZ   (128 * AROW)          // 34816 (one 128-row K or V tile)
#define ASTG_VH  AKT_SZ
#define ASTG_SZ  (2 * AKT_SZ)          // 69632
#define ATT_SMEM (2 * ASTG_SZ)         // 139264

__device__ __forceinline__ void att_load_kv(
    uint32_t dst, const __half* khb, const __half* vhb, int n0, int t)
{
#pragma unroll
    for (int i = 0; i < 8; ++i) {
        int id = t + i * 256;
        int r  = id >> 4, c = id & 15;
        uint32_t o  = r * AROW + c * 16;
        size_t   go = (size_t)(n0 + r) * KVD + c * 8;
        CP_ASYNC16(dst + o, khb + go);
        CP_ASYNC16(dst + ASTG_VH + o, vhb + go);
    }
}

__global__ __launch_bounds__(256, 1) void attn_mma(
    const __half* __restrict__ qh, const __half* __restrict__ ql,
    const __half* __restrict__ kh, const __half* __restrict__ vh,
    __half* __restrict__ cc)
{
    extern __shared__ char sm[];
    const int b   = blockIdx.z;
    const int h   = blockIdx.y;
    const int mb  = gridDim.x - 1 - blockIdx.x;
    const int m0  = mb * 128;
    const int kvh = h / GROUP;
    const int t    = threadIdx.x;
    const int lane = t & 31;
    const int w    = t >> 5;

    const uint32_t sb  = smem_u32(sm);
    const uint32_t sQh = sb + ASTG_SZ;          // temp: stage-1 region
    const uint32_t sQl = sQh + AKT_SZ;

    const __half* qhb = qh + ((size_t)(b*SS + m0) * QH + h) * HD;
    const __half* qlb = ql + ((size_t)(b*SS + m0) * QH + h) * HD;
    const __half* khb = kh + ((size_t)b*SS*KVH + kvh) * HD;
    const __half* vhb = vh + ((size_t)b*SS*KVH + kvh) * HD;

    const int ntiles = mb + 1;     // 128-col tiles up to and incl. diagonal

    // group 0: Q (into stage-1 region) + kv0 (stage 0)
#pragma unroll
    for (int i = 0; i < 8; ++i) {
        int id = t + i * 256;
        int r  = id >> 4, c = id & 15;
        uint32_t o  = r * AROW + c * 16;
        size_t   go = (size_t)r * (QH*HD) + c * 8;
        CP_ASYNC16(sQh + o, qhb + go);
        CP_ASYNC16(sQl + o, qlb + go);
    }
    att_load_kv(sb, khb, vhb, 0, t);
    CP_COMMIT();

    const uint32_t qoff = (w * 16 + (lane & 15)) * AROW + ((lane >> 4) << 4);
    const uint32_t koff = (lane & 15) * AROW + ((lane >> 4) << 4);
    const int vrow = (lane & 7) + ((lane >> 4) << 3);
    const uint32_t vcol = ((lane >> 3) & 1) << 4;

    // one-time Q register load (drains group 0)
    CP_WAIT(0);
    __syncthreads();
    uint32_t Aq[8][4], Al[8][4];
#pragma unroll
    for (int ch = 0; ch < 8; ++ch) {
        LDM_X4(Aq[ch][0], Aq[ch][1], Aq[ch][2], Aq[ch][3], sQh + qoff + ch * 32);
        LDM_X4(Al[ch][0], Al[ch][1], Al[ch][2], Al[ch][3], sQl + qoff + ch * 32);
    }
    __syncthreads();   // Q consumed -> stage 1 free
    // group 1: kv1 into stage 1 (empty group if ntiles == 1)
    if (ntiles > 1) att_load_kv(sb + ASTG_SZ, khb, vhb, 128, t);
    CP_COMMIT();

    float O[16][4];
#pragma unroll
    for (int i = 0; i < 16; i++)
#pragma unroll
        for (int j = 0; j < 4; j++) O[i][j] = 0.f;
    float mx0 = -INFINITY, mx1 = -INFINITY, l0 = 0.f, l1 = 0.f;

    const int row0 = m0 + w * 16 + (lane >> 2);
    const int row1 = row0 + 8;
    const int wrow_hi = m0 + w * 16 + 15;
    const int wrow_lo = m0 + w * 16;

    for (int it = 0; it < ntiles; ++it) {
        const int n0 = it * 128;
        // ensure kv(it) loaded: leave only the newest group (kv(it+1)) pending
        if (it > 0) CP_WAIT(1);
        __syncthreads();
        const uint32_t stg = sb + (it & 1) * ASTG_SZ;

        if (n0 <= wrow_hi) {
            float S[16][4];
#pragma unroll
            for (int i = 0; i < 16; i++)
#pragma unroll
                for (int j = 0; j < 4; j++) S[i][j] = 0.f;

            // S = (Qh + Ql) @ K^T over 128 key rows (8 p-groups of 16)
#pragma unroll
            for (int ch = 0; ch < 8; ++ch) {
#pragma unroll
                for (int p = 0; p < 8; ++p) {
                    uint32_t h0,h1,h2,h3;
                    LDM_X4(h0,h1,h2,h3, stg + koff + p*(16*AROW) + ch*32);
                    uint32_t bh0[2] = {h0, h2}, bh1[2] = {h1, h3};
                    MMA16816(S[2*p],   Aq[ch], bh0);
                    MMA16816(S[2*p+1], Aq[ch], bh1);
                    MMA16816(S[2*p],   Al[ch], bh0);
                    MMA16816(S[2*p+1], Al[ch], bh1);
                }
            }

            if (n0 + 127 > wrow_lo) {
#pragma unroll
                for (int p = 0; p < 16; ++p) {
                    int c = n0 + p * 8 + (lane & 3) * 2;
                    if (c     > row0) S[p][0] = -INFINITY;
                    if (c + 1 > row0) S[p][1] = -INFINITY;
                    if (c     > row1) S[p][2] = -INFINITY;
                    if (c + 1 > row1) S[p][3] = -INFINITY;
                }
            }

            float t0 = -INFINITY, t1 = -INFINITY;
#pragma unroll
            for (int p = 0; p < 16; ++p) {
                t0 = fmaxf(t0, fmaxf(S[p][0], S[p][1]));
                t1 = fmaxf(t1, fmaxf(S[p][2], S[p][3]));
            }
            t0 = fmaxf(t0, __shfl_xor_sync(0xffffffffu, t0, 1));
            t0 = fmaxf(t0, __shfl_xor_sync(0xffffffffu, t0, 2));
            t1 = fmaxf(t1, __shfl_xor_sync(0xffffffffu, t1, 1));
            t1 = fmaxf(t1, __shfl_xor_sync(0xffffffffu, t1, 2));
            float mn0 = fmaxf(mx0, t0), mn1 = fmaxf(mx1, t1);
            float cr0 = ex2f(mx0 - mn0), cr1 = ex2f(mx1 - mn1);
            mx0 = mn0; mx1 = mn1;

            float sa0 = 0.f, sa1 = 0.f;
#pragma unroll
            for (int p = 0; p < 16; ++p) {
                S[p][0] = ex2f(S[p][0] - mn0);
                S[p][1] = ex2f(S[p][1] - mn0);
                S[p][2] = ex2f(S[p][2] - mn1);
                S[p][3] = ex2f(S[p][3] - mn1);
                sa0 += S[p][0] + S[p][1];
                sa1 += S[p][2] + S[p][3];
            }
            sa0 += __shfl_xor_sync(0xffffffffu, sa0, 1);
            sa0 += __shfl_xor_sync(0xffffffffu, sa0, 2);
            sa1 += __shfl_xor_sync(0xffffffffu, sa1, 1);
            sa1 += __shfl_xor_sync(0xffffffffu, sa1, 2);
            l0 = l0 * cr0 + sa0;
            l1 = l1 * cr1 + sa1;

#pragma unroll
            for (int i = 0; i < 16; i++) {
                O[i][0] *= cr0; O[i][1] *= cr0;
                O[i][2] *= cr1; O[i][3] *= cr1;
            }

            // O += P @ V over 128 key rows (8 jc-groups of 16)
#pragma unroll
            for (int jc = 0; jc < 8; ++jc) {
                uint32_t ph[4];
#pragma unroll
                for (int q2 = 0; q2 < 2; ++q2) {
                    ph[2*q2]   = pack_f16(S[2*jc + q2][0], S[2*jc + q2][1]);
                    ph[2*q2+1] = pack_f16(S[2*jc + q2][2], S[2*jc + q2][3]);
                }
                const uint32_t vro = (jc * 16 + vrow) * AROW + vcol;
#pragma unroll
                for (int db = 0; db < 8; ++db) {
                    uint32_t a0,a1,a2,a3;
                    LDM_X4T(a0,a1,a2,a3, stg + ASTG_VH + vro + db * 32);
                    uint32_t bh0[2] = {a0, a2}, bh1[2] = {a1, a3};
                    MMA16816(O[2*db],   ph, bh0);
                    MMA16816(O[2*db+1], ph, bh1);
                }
            }
        }

        __syncthreads();   // all warps done reading stage it&1
        if (it + 2 < ntiles)
            att_load_kv(stg, khb, vhb, (it + 2) * 128, t);
        CP_COMMIT();       // unconditional: keeps group accounting uniform
    }

    // normalize + single fp16 write to cc (row length DD)
    float inv0 = 1.0f / l0, inv1 = 1.0f / l1;
    const size_t base0 = (size_t)(b * SS + row0) * DD;
    const size_t base1 = (size_t)(b * SS + row1) * DD;
    const int colb = h * 128 + (lane & 3) * 2;
#pragma unroll
    for (int dt = 0; dt < 16; ++dt) {
        int col = colb + dt * 8;
        *(uint32_t*)(cc + base0 + col) = pack_f16(O[dt][0] * inv0, O[dt][1] * inv0);
        *(uint32_t*)(cc + base1 + col) = pack_f16(O[dt][2] * inv1, O[dt][3] * inv1);
    }
}

// ---------------------------------------------------------------------------
// launch
// ---------------------------------------------------------------------------
extern "C" void kernel_launch(void* const* d_in, const int* in_sizes, int n_in,
                              void* d_out, int out_size)
{
    const float* xs   = (const float*)d_in[0];
    const int*   spos = (const int*)  d_in[1];
    const float* fc   = (const float*)d_in[2];
    const float* Wq   = (const float*)d_in[3];
    const float* bq   = (const float*)d_in[4];
    const float* Wk   = (const float*)d_in[5];
    const float* bk   = (const float*)d_in[6];
    const float* Wv   = (const float*)d_in[7];
    const float* bv   = (const float*)d_in[8];
    const float* Wo   = (const float*)d_in[9];
    const float* bo   = (const float*)d_in[10];
    float* out = (float*)d_out;

    __half *xc, *wqkv, *woc, *cc, *qhp, *qlp, *khp, *vhp;
    cudaGetSymbolAddress((void**)&xc,   g_xc);
    cudaGetSymbolAddress((void**)&wqkv, g_wqkv);
    cudaGetSymbolAddress((void**)&woc,  g_woc);
    cudaGetSymbolAddress((void**)&cc,   g_cc);
    cudaGetSymbolAddress((void**)&qhp,  g_qh);
    cudaGetSymbolAddress((void**)&qlp,  g_ql);
    cudaGetSymbolAddress((void**)&khp,  g_kh);
    cudaGetSymbolAddress((void**)&vhp,  g_vh);

    cudaFuncSetAttribute(gemm_qkv, cudaFuncAttributeMaxDynamicSharedMemorySize, GSMEM);
    cudaFuncSetAttribute(gemm_out, cudaFuncAttributeMaxDynamicSharedMemorySize, OSMEM);
    cudaFuncSetAttribute(attn_mma, cudaFuncAttributeMaxDynamicSharedMemorySize, ATT_SMEM);

    // fused conversions (launch 1)
    convert_all<<<(CNTOT + 255) / 256, 256>>>(xs, Wq, Wk, Wv, Wo, xc, wqkv, woc);

    // fused QKV projection + rope + split (launch 2)
    gemm_qkv<<<dim3(TOK/CTM, NQKV/CTN), 256, GSMEM>>>(
        xc, wqkv, bq, bk, bv, fc, spos, qhp, qlp, khp, vhp);

    // attention (launch 3)
    attn_mma<<<dim3(SS/128, QH, BB), 256, ATT_SMEM>>>(qhp, qlp, khp, vhp, cc);

    // output projection (launch 4)
    gemm_out<<<dim3(TOK/CTM, DD/CTN), 256, OSMEM>>>(cc, woc, bo, out, DD);
}